// round 16
// baseline (speedup 1.0000x reference)
#include <cuda_runtime.h>
#include <cooperative_groups.h>
#include <math.h>

namespace cg = cooperative_groups;

#define NND   8192
#define FIN   1280
#define HH    320
#define EE    131072
#define GGR   1024
#define CHUNK 128
#define NCH   (NND / CHUNK)        // 64 chunks
#define NTILE (FIN / 128)          // 10 n-tiles per chunk
#define TASKS_PER (NCH * NTILE)    // 640
#define ZTILE 5                    // 320/64 n-tiles for GCN layer-1 z
#define ZTASKS (NCH * ZTILE)       // 320
#define NTASKS_TOTAL (2 * TASKS_PER + ZTASKS)

// ---------------- scratch (device globals) ----------------
__device__ float g_gx0[NND * FIN];
__device__ float g_gx1[NND * FIN];
__device__ float g_h0[NND * HH];
__device__ float g_h1[NND * HH];
__device__ float g_z [NND * HH];
__device__ float g_y [NND * HH];
__device__ float g_mu[64];
__device__ float g_rstd[64];
__device__ int   g_cnt0[NCH];
__device__ int   g_cnt1[NCH];
__device__ int   g_hflag0[NCH * 16];
__device__ int   g_hflag1[NCH * 16];
__device__ int   g_q;

__device__ __forceinline__ float lrelu(float x) { return x > 0.f ? x : 0.01f * x; }

// HW tanh approx (MUFU.TANH): verified rel_err-neutral since R7
__device__ __forceinline__ float tanha(float x) {
    float r;
    asm("tanh.approx.f32 %0, %1;" : "=f"(r) : "f"(x));
    return r;
}
__device__ __forceinline__ float sigma(float x) {
    return fmaf(0.5f, tanha(0.5f * x), 0.5f);
}

__device__ __forceinline__ unsigned s2u(const void* p) {
    unsigned a;
    asm("{ .reg .u64 t; cvta.to.shared.u64 t, %1; cvt.u32.u64 %0, t; }" : "=r"(a) : "l"(p));
    return a;
}
__device__ __forceinline__ int ld_acq(const int* p) {
    int v;
    asm volatile("ld.global.acquire.gpu.s32 %0, [%1];" : "=r"(v) : "l"(p));
    return v;
}
__device__ __forceinline__ void st_rel(int* p, int v) {
    asm volatile("st.global.release.gpu.s32 [%0], %1;" :: "l"(p), "r"(v));
}
// low-traffic flag wait: fast-path check, then 4us-period polling
__device__ __forceinline__ void flag_wait(const int* p) {
    if (ld_acq(p) != 0) return;
    while (ld_acq(p) == 0) __nanosleep(4000);
}

// packed fp32x2 fma helpers
__device__ __forceinline__ void fma2(unsigned long long& d,
                                     unsigned long long a, unsigned long long b) {
    asm("fma.rn.f32x2 %0, %1, %2, %0;" : "+l"(d) : "l"(a), "l"(b));
}
__device__ __forceinline__ unsigned long long pack2(float lo, float hi) {
    unsigned long long r;
    asm("mov.b64 %0, {%1, %2};" : "=l"(r) : "f"(lo), "f"(hi));
    return r;
}
__device__ __forceinline__ void unpack2(unsigned long long v, float& lo, float& hi) {
    asm("mov.b64 {%0, %1}, %2;" : "=f"(lo), "=f"(hi) : "l"(v));
}

__device__ __forceinline__ void mbar_init(unsigned addr, unsigned cnt) {
    asm volatile("mbarrier.init.shared.b64 [%0], %1;" :: "r"(addr), "r"(cnt) : "memory");
}
__device__ __forceinline__ void mbar_arrive_local(unsigned addr) {
    asm volatile("mbarrier.arrive.shared.b64 _, [%0];" :: "r"(addr) : "memory");
}
__device__ __forceinline__ void mbar_expect_tx(unsigned addr, unsigned bytes) {
    asm volatile("mbarrier.arrive.expect_tx.shared.b64 _, [%0], %1;"
                 :: "r"(addr), "r"(bytes) : "memory");
}
__device__ __forceinline__ void mbar_wait(unsigned addr, unsigned parity) {
    asm volatile(
        "{\n\t"
        ".reg .pred P;\n\t"
        "WLP_%=:\n\t"
        "mbarrier.try_wait.parity.acquire.cluster.shared::cta.b64 P, [%0], %1, 0x989680;\n\t"
        "@P bra WDN_%=;\n\t"
        "bra WLP_%=;\n\t"
        "WDN_%=:\n\t"
        "}"
        :: "r"(addr), "r"(parity) : "memory");
}
__device__ __forceinline__ unsigned mapa_rank(unsigned addr, unsigned rank) {
    unsigned r;
    asm("mapa.shared::cluster.u32 %0, %1, %2;" : "=r"(r) : "r"(addr), "r"(rank));
    return r;
}
__device__ __forceinline__ void st_async64(unsigned daddr, unsigned maddr,
                                           unsigned long long val) {
    asm volatile(
        "st.async.shared::cluster.mbarrier::complete_tx::bytes.b64 [%0], %1, [%2];"
        :: "r"(daddr), "l"(val), "r"(maddr) : "memory");
}

// ---------------- worker: 128x128 fp32 tile GEMM (512 threads) ----------------
__device__ void gemm_tile_128(const float* __restrict__ A, int lda,
                              const float* __restrict__ B, int ldb,
                              float* __restrict__ C, int ldc, int K,
                              const float* __restrict__ b0,
                              const float* __restrict__ b1)
{
    __shared__ __align__(16) float As[16][132];
    __shared__ __align__(16) float Bs[16][136];
    const int tid = threadIdx.x;
    const int tx = tid & 31;
    const int ty = tid >> 5;

    float acc[8][4];
#pragma unroll
    for (int i = 0; i < 8; i++)
#pragma unroll
        for (int j = 0; j < 4; j++) acc[i][j] = 0.f;

    for (int k0 = 0; k0 < K; k0 += 16) {
#pragma unroll
        for (int r = 0; r < 4; r++) {
            int idx = tid + r * 512;
            int m = idx >> 4, kk = idx & 15;
            As[kk][m] = A[(size_t)m * lda + k0 + kk];
        }
#pragma unroll
        for (int r = 0; r < 4; r++) {
            int idx = tid + r * 512;
            int n = idx >> 4, kk = idx & 15;
            Bs[kk][n] = B[(size_t)n * ldb + k0 + kk];
        }
        __syncthreads();
#pragma unroll
        for (int kk = 0; kk < 16; kk++) {
            float4 b = *(const float4*)&Bs[kk][tx * 4];
            float a[8];
#pragma unroll
            for (int i = 0; i < 8; i++) a[i] = As[kk][ty * 8 + i];
#pragma unroll
            for (int i = 0; i < 8; i++) {
                acc[i][0] = fmaf(a[i], b.x, acc[i][0]);
                acc[i][1] = fmaf(a[i], b.y, acc[i][1]);
                acc[i][2] = fmaf(a[i], b.z, acc[i][2]);
                acc[i][3] = fmaf(a[i], b.w, acc[i][3]);
            }
        }
        __syncthreads();
    }
#pragma unroll
    for (int i = 0; i < 8; i++) {
        int m = ty * 8 + i;
#pragma unroll
        for (int j = 0; j < 4; j++) {
            int n = tx * 4 + j;
            C[(size_t)m * ldc + n] = acc[i][j] + b0[n] + b1[n];
        }
    }
}

// GCN layer-1 z tile: C[128,64] = lrelu(A[128,K]) @ B[K x 64-slice]
__device__ void gemm_tile_z(const float* __restrict__ A,
                            const float* __restrict__ B,
                            float* __restrict__ C, int ldc, int K)
{
    __shared__ __align__(16) float Az[16][132];
    __shared__ __align__(16) float Bz[16][68];
    const int tid = threadIdx.x;
    const int tx = tid & 15;
    const int ty = tid >> 4;

    float acc[4][4];
#pragma unroll
    for (int i = 0; i < 4; i++)
#pragma unroll
        for (int j = 0; j < 4; j++) acc[i][j] = 0.f;

    for (int k0 = 0; k0 < K; k0 += 16) {
#pragma unroll
        for (int r = 0; r < 4; r++) {
            int idx = tid + r * 512;
            int m = idx >> 4, kk = idx & 15;
            Az[kk][m] = lrelu(A[(size_t)m * K + k0 + kk]);
        }
#pragma unroll
        for (int r = 0; r < 2; r++) {
            int idx = tid + r * 512;
            int kk = idx >> 6, nn = idx & 63;
            Bz[kk][nn] = B[(size_t)(k0 + kk) * HH + nn];
        }
        __syncthreads();
#pragma unroll
        for (int kk = 0; kk < 16; kk++) {
            float4 b = *(const float4*)&Bz[kk][tx * 4];
            float a[4];
#pragma unroll
            for (int i = 0; i < 4; i++) a[i] = Az[kk][ty * 4 + i];
#pragma unroll
            for (int i = 0; i < 4; i++) {
                acc[i][0] = fmaf(a[i], b.x, acc[i][0]);
                acc[i][1] = fmaf(a[i], b.y, acc[i][1]);
                acc[i][2] = fmaf(a[i], b.z, acc[i][2]);
                acc[i][3] = fmaf(a[i], b.w, acc[i][3]);
            }
        }
        __syncthreads();
    }
#pragma unroll
    for (int i = 0; i < 4; i++) {
        int m = ty * 4 + i;
#pragma unroll
        for (int j = 0; j < 4; j++)
            C[(size_t)m * ldc + tx * 4 + j] = acc[i][j];
    }
}

__device__ void worker_body(const float* __restrict__ x,
                            const float* __restrict__ Wih0,
                            const float* __restrict__ bih0,
                            const float* __restrict__ bhh0,
                            const float* __restrict__ Wih1,
                            const float* __restrict__ bih1,
                            const float* __restrict__ bhh1,
                            const float* __restrict__ Wg1,
                            int ncta)
{
    __shared__ int task_s;
    const int tid = threadIdx.x;
    for (;;) {
        if (tid == 0) task_s = atomicAdd(&g_q, 1);
        __syncthreads();
        const int task = task_s;
        __syncthreads();
        if (task >= NTASKS_TOTAL) return;
        if (task < TASKS_PER) {
            int k = task / NTILE, nt = task % NTILE;
            gemm_tile_128(x + (size_t)k * CHUNK * FIN, FIN,
                          Wih0 + (size_t)nt * 128 * FIN, FIN,
                          g_gx0 + (size_t)k * CHUNK * FIN + nt * 128, FIN, FIN,
                          bih0 + nt * 128, bhh0 + nt * 128);
            __threadfence();
            __syncthreads();
            if (tid == 0) atomicAdd(&g_cnt0[k], 1);
        } else if (task < 2 * TASKS_PER) {
            int t2 = task - TASKS_PER;
            int k = t2 / NTILE, nt = t2 % NTILE;
            if (tid == 0) {
                for (int r = 0; r < ncta; r++)
                    flag_wait(&g_hflag0[k * 16 + r]);
            }
            __syncthreads();
            gemm_tile_128(g_h0 + (size_t)k * CHUNK * HH, HH,
                          Wih1 + (size_t)nt * 128 * HH, HH,
                          g_gx1 + (size_t)k * CHUNK * FIN + nt * 128, FIN, HH,
                          bih1 + nt * 128, bhh1 + nt * 128);
            __threadfence();
            __syncthreads();
            if (tid == 0) atomicAdd(&g_cnt1[k], 1);
        } else {
            int t3 = task - 2 * TASKS_PER;
            int k = t3 / ZTILE, nt = t3 % ZTILE;
            if (tid == 0) {
                for (int r = 0; r < ncta; r++)
                    flag_wait(&g_hflag1[k * 16 + r]);
            }
            __syncthreads();
            gemm_tile_z(g_h1 + (size_t)k * CHUNK * HH,
                        Wg1 + nt * 64,
                        g_z + (size_t)k * CHUNK * HH + nt * 64, HH, HH);
            __syncthreads();
        }
    }
}

// ---------------- LSTM scan: R8 body EXACT (proven 7.37ms) ----------------
template<int NCTA>
__device__ void scan_body(const float* __restrict__ gx,
                          const float* __restrict__ Whh,
                          float* __restrict__ hs,
                          int* __restrict__ cnt,
                          int* __restrict__ hflag)
{
    constexpr int U  = HH / NCTA;
    constexpr int RW = (4 * U) / 16;

    cg::cluster_group cluster = cg::this_cluster();
    const unsigned rank = cluster.block_rank();
    const int tid = threadIdx.x;
    const int w = tid >> 5, lane = tid & 31;

    __shared__ alignas(8) float h_s[2][HH];
    __shared__ alignas(8) float gates_s[4 * U];
    __shared__ alignas(8) float c_s[U];
    __shared__ alignas(8) unsigned long long mbar[2];

    const unsigned mb0 = s2u(&mbar[0]);
    const unsigned mb1 = s2u(&mbar[1]);

    unsigned long long wr2[RW][5];
#pragma unroll
    for (int rr = 0; rr < RW; rr++) {
        int r = w * RW + rr;
        int gate = r / U;
        int jj = r - gate * U;
        int grow = gate * HH + (int)rank * U + jj;
        const float2* wp = (const float2*)(Whh + (size_t)grow * HH);
#pragma unroll
        for (int p = 0; p < 5; p++) {
            float2 v = wp[lane + 32 * p];
            wr2[rr][p] = pack2(v.x, v.y);
        }
    }

    if (tid < HH) h_s[0][tid] = 0.f;
    if (tid < U) c_s[tid] = 0.f;
    if (tid == 0) {
        mbar_init(mb0, 1);
        mbar_init(mb1, 1);
        mbar_arrive_local(mb0);
        mbar_expect_tx(mb1, 1280);
    }
    cluster.sync();

    const int jg = (int)rank * U + 2 * tid;
    const float* gxp = gx + jg;

    unsigned dmap[NCTA], mmap[NCTA];
    if (tid < U / 2) {
        const unsigned ha0 = s2u(&h_s[0][jg]);
#pragma unroll
        for (unsigned r = 0; r < (unsigned)NCTA; r++) {
            dmap[r] = mapa_rank(ha0, r);
            mmap[r] = mapa_rank(mb0, r);
        }
    }

    for (int t = 0; t < NND; t++) {
        if ((t & (CHUNK - 1)) == 0) {
            if (tid == 0) {
                int k = t >> 7;
                while (ld_acq(&cnt[k]) < NTILE) __nanosleep(100);
            }
            __syncthreads();
        }

        const int cur = t & 1;
        const unsigned mcur = cur ? mb1 : mb0;

        float2 gxv[4];
        if (tid < U / 2) {
#pragma unroll
            for (int g = 0; g < 4; g++)
                gxv[g] = __ldg((const float2*)(gxp + (size_t)t * FIN + g * HH));
        }

        if (t > 0) mbar_wait(mcur, (t >> 1) & 1);
        if (tid == 32) mbar_expect_tx(mcur, 1280);

        const float2* hp = (const float2*)h_s[cur];
        unsigned long long acc2[RW];
#pragma unroll
        for (int rr = 0; rr < RW; rr++) acc2[rr] = 0ULL;
#pragma unroll
        for (int p = 0; p < 5; p++) {
            float2 hv = hp[lane + 32 * p];
            unsigned long long hv2 = pack2(hv.x, hv.y);
#pragma unroll
            for (int rr = 0; rr < RW; rr++) fma2(acc2[rr], wr2[rr][p], hv2);
        }
        float s[RW];
#pragma unroll
        for (int rr = 0; rr < RW; rr++) {
            float a0, a1;
            unpack2(acc2[rr], a0, a1);
            s[rr] = a0 + a1;
        }
#pragma unroll
        for (int off = 16; off > 0; off >>= 1)
#pragma unroll
            for (int rr = 0; rr < RW; rr++)
                s[rr] += __shfl_xor_sync(0xffffffffu, s[rr], off);
        if (lane == 0) {
#pragma unroll
            for (int rr = 0; rr < RW; rr++) gates_s[w * RW + rr] = s[rr];
        }
        __syncthreads();

        if (tid < U / 2) {
            const float2* gp = (const float2*)gates_s;
            float2 Gi = gp[tid];
            float2 Gf = gp[U / 2 + tid];
            float2 Gg = gp[U + tid];
            float2 Go = gp[3 * U / 2 + tid];
            float i0 = Gi.x + gxv[0].x, i1 = Gi.y + gxv[0].y;
            float f0 = Gf.x + gxv[1].x, f1 = Gf.y + gxv[1].y;
            float g0 = Gg.x + gxv[2].x, g1 = Gg.y + gxv[2].y;
            float o0 = Go.x + gxv[3].x, o1 = Go.y + gxv[3].y;
            float2 c = *(float2*)&c_s[2 * tid];
            c.x = sigma(f0) * c.x + sigma(i0) * tanha(g0);
            c.y = sigma(f1) * c.y + sigma(i1) * tanha(g1);
            float h0v = sigma(o0) * tanha(c.x);
            float h1v = sigma(o1) * tanha(c.y);
            *(float2*)&c_s[2 * tid] = c;
            unsigned long long hh = pack2(h0v, h1v);
            *(unsigned long long*)&hs[(size_t)t * HH + jg] = hh;
            const unsigned doff = (cur ^ 1) ? (unsigned)(HH * 4) : 0u;
            const unsigned moff = (cur ^ 1) ? 8u : 0u;
#pragma unroll
            for (unsigned r = 0; r < (unsigned)NCTA; r++)
                st_async64(dmap[r] + doff, mmap[r] + moff, hh);
        }

        if ((t & (CHUNK - 1)) == (CHUNK - 1)) {
            __threadfence();
            __syncthreads();
            if (tid == 0) st_rel(&hflag[(t >> 7) * 16 + (int)rank], 1);
        }
    }

    mbar_wait(mb0, (NND >> 1) & 1);
    cluster.sync();
}

// ---------------- fused persistent kernel ----------------
__global__ void __launch_bounds__(512, 1)
fused_kernel(const float* __restrict__ x,
             const float* __restrict__ Wih0, const float* __restrict__ bih0,
             const float* __restrict__ bhh0, const float* __restrict__ Whh0,
             const float* __restrict__ Wih1, const float* __restrict__ bih1,
             const float* __restrict__ bhh1, const float* __restrict__ Whh1,
             const float* __restrict__ Wg1, int ncta)
{
    const int bid = blockIdx.x;
    if (ncta == 16) {
        if (bid < 16)      scan_body<16>(g_gx0, Whh0, g_h0, g_cnt0, g_hflag0);
        else if (bid < 32) scan_body<16>(g_gx1, Whh1, g_h1, g_cnt1, g_hflag1);
        else worker_body(x, Wih0, bih0, bhh0, Wih1, bih1, bhh1, Wg1, 16);
    } else {
        if (bid < 8)       scan_body<8>(g_gx0, Whh0, g_h0, g_cnt0, g_hflag0);
        else if (bid < 16) scan_body<8>(g_gx1, Whh1, g_h1, g_cnt1, g_hflag1);
        else worker_body(x, Wih0, bih0, bhh0, Wih1, bih1, bhh1, Wg1, 8);
    }
}

__global__ void reset_kernel()
{
    int i = blockIdx.x * blockDim.x + threadIdx.x;
    if (i < NCH) { g_cnt0[i] = 0; g_cnt1[i] = 0; }
    if (i < NCH * 16) { g_hflag0[i] = 0; g_hflag1[i] = 0; }
    if (i == 0) g_q = 0;
}

// ---------------- GCN-path fp32 GEMM (layers 2-4) ----------------
template<int TRANSB, int LRA>
__global__ void __launch_bounds__(256) sgemm_kernel(
    int M, int N, int K,
    const float* __restrict__ A, const float* __restrict__ B,
    float* __restrict__ C,
    const float* __restrict__ bias0, const float* __restrict__ bias1)
{
    __shared__ float As[16][132];
    __shared__ float Bs[16][68];
    const int tid = threadIdx.x;
    const int tx = tid & 15;
    const int ty = tid >> 4;
    const int bm = blockIdx.y * 128;
    const int bn = blockIdx.x * 64;

    float acc[8][4];
#pragma unroll
    for (int i = 0; i < 8; i++)
#pragma unroll
        for (int j = 0; j < 4; j++) acc[i][j] = 0.f;

    for (int k0 = 0; k0 < K; k0 += 16) {
#pragma unroll
        for (int r = 0; r < 8; r++) {
            int idx = tid + r * 256;
            int m = idx >> 4, kk = idx & 15;
            int kg = k0 + kk;
            float v = 0.f;
            if (kg < K) {
                v = A[(size_t)(bm + m) * K + kg];
                if (LRA) v = lrelu(v);
            }
            As[kk][m] = v;
        }
#pragma unroll
        for (int r = 0; r < 4; r++) {
            int idx = tid + r * 256;
            float v = 0.f;
            if (TRANSB) {
                int nn = idx >> 4, kk = idx & 15;
                if (bn + nn < N && k0 + kk < K) v = B[(size_t)(bn + nn) * K + k0 + kk];
                Bs[kk][nn] = v;
            } else {
                int kk = idx >> 6, nn = idx & 63;
                if (k0 + kk < K && bn + nn < N) v = B[(size_t)(k0 + kk) * N + bn + nn];
                Bs[kk][nn] = v;
            }
        }
        __syncthreads();
#pragma unroll
        for (int kk = 0; kk < 16; kk++) {
            float a[8], b[4];
#pragma unroll
            for (int i = 0; i < 8; i++) a[i] = As[kk][ty * 8 + i];
#pragma unroll
            for (int j = 0; j < 4; j++) b[j] = Bs[kk][tx * 4 + j];
#pragma unroll
            for (int i = 0; i < 8; i++)
#pragma unroll
                for (int j = 0; j < 4; j++) acc[i][j] = fmaf(a[i], b[j], acc[i][j]);
        }
        __syncthreads();
    }
#pragma unroll
    for (int i = 0; i < 8; i++) {
        int m = bm + ty * 8 + i;
#pragma unroll
        for (int j = 0; j < 4; j++) {
            int n = bn + tx * 4 + j;
            if (n < N) {
                float v = acc[i][j];
                if (bias0) v += bias0[n];
                if (bias1) v += bias1[n];
                C[(size_t)m * N + n] = v;
            }
        }
    }
}

// ---------------- GCN scatter (vector atomics) ----------------
__global__ void init_bias_kernel(float* __restrict__ y, const float* __restrict__ b, int F)
{
    int idx = blockIdx.x * 256 + threadIdx.x;
    if (idx < NND * F) y[idx] = b[idx % F];
}

template<int VEC>
__global__ void scatter_kernel(const float* __restrict__ z, const int* __restrict__ ei,
                               const float* __restrict__ ew, float* __restrict__ y, int F)
{
    long long idx = (long long)blockIdx.x * blockDim.x + threadIdx.x;
    int nv = F / VEC;
    long long total = (long long)EE * nv;
    if (idx >= total) return;
    int e  = (int)(idx / nv);
    int fv = (int)(idx - (long long)e * nv);
    int s = ei[e];
    int d = ei[EE + e];
    float wv = ew[e];
    if (VEC == 4) {
        float4 v = *(const float4*)(z + (size_t)s * F + 4 * fv);
        float4 m = make_float4(v.x * wv, v.y * wv, v.z * wv, v.w * wv);
        atomicAdd((float4*)(y + (size_t)d * F + 4 * fv), m);
    } else {
        float2 v = *(const float2*)(z + (size_t)s * F + 2 * fv);
        float2 m = make_float2(v.x * wv, v.y * wv);
        atomicAdd((float2*)(y + (size_t)d * F + 2 * fv), m);
    }
}

// ---------------- BatchNorm stats ----------------
__global__ void bn_stats_kernel(const float* __restrict__ y)
{
    int f = blockIdx.x;
    int tid = threadIdx.x;
    __shared__ float red[256];
    __shared__ float mu_s;

    float s = 0.f;
    for (int i = tid; i < NND; i += 256) s += y[(size_t)i * 50 + f];
    red[tid] = s; __syncthreads();
    for (int st = 128; st > 0; st >>= 1) {
        if (tid < st) red[tid] += red[tid + st];
        __syncthreads();
    }
    if (tid == 0) mu_s = red[0] * (1.f / (float)NND);
    __syncthreads();
    float mu = mu_s;

    float s2 = 0.f;
    for (int i = tid; i < NND; i += 256) {
        float d = y[(size_t)i * 50 + f] - mu;
        s2 += d * d;
    }
    red[tid] = s2; __syncthreads();
    for (int st = 128; st > 0; st >>= 1) {
        if (tid < st) red[tid] += red[tid + st];
        __syncthreads();
    }
    if (tid == 0) {
        g_mu[f] = mu;
        g_rstd[f] = rsqrtf(red[0] * (1.f / (float)NND) + 1e-5f);
    }
}

// ---------------- BN apply + lrelu + pool + FC ----------------
__global__ void __launch_bounds__(128) bn_pool_fc_kernel(
    const float* __restrict__ y,
    const float* __restrict__ gamma, const float* __restrict__ beta,
    const float* __restrict__ fc1W, const float* __restrict__ fc1b,
    const float* __restrict__ fc2W, const float* __restrict__ fc2b,
    const float* __restrict__ fc3W, const float* __restrict__ fc3b,
    float* __restrict__ out)
{
    int g = blockIdx.x * blockDim.x + threadIdx.x;
    if (g >= GGR) return;

    float pooled[50];
#pragma unroll
    for (int f = 0; f < 50; f++) pooled[f] = 0.f;
    for (int k = 0; k < 8; k++) {
        const float* row = y + (size_t)(g * 8 + k) * 50;
#pragma unroll
        for (int f = 0; f < 50; f++) {
            float v = row[f];
            float bn = gamma[f] * (v - g_mu[f]) * g_rstd[f] + beta[f];
            pooled[f] += lrelu(bn);
        }
    }
    float h1[30];
    for (int n = 0; n < 30; n++) {
        float s = fc1b[n];
#pragma unroll
        for (int k = 0; k < 50; k++) s = fmaf(pooled[k], fc1W[k * 30 + n], s);
        h1[n] = lrelu(s);
    }
    float h2[20];
    for (int n = 0; n < 20; n++) {
        float s = fc2b[n];
#pragma unroll
        for (int k = 0; k < 30; k++) s = fmaf(h1[k], fc2W[k * 20 + n], s);
        h2[n] = lrelu(s);
    }
    for (int n = 0; n < 2; n++) {
        float s = fc3b[n];
#pragma unroll
        for (int k = 0; k < 20; k++) s = fmaf(h2[k], fc3W[k * 2 + n], s);
        out[g * 2 + n] = lrelu(s);
    }
}

// ---------------- launch ----------------
extern "C" void kernel_launch(void* const* d_in, const int* in_sizes, int n_in,
                              void* d_out, int out_size)
{
    const float* x    = (const float*)d_in[0];
    const int*   ei   = (const int*)  d_in[1];
    const float* ew   = (const float*)d_in[2];
    const float* Wih0 = (const float*)d_in[4];
    const float* Whh0 = (const float*)d_in[5];
    const float* bih0 = (const float*)d_in[6];
    const float* bhh0 = (const float*)d_in[7];
    const float* Wih1 = (const float*)d_in[8];
    const float* Whh1 = (const float*)d_in[9];
    const float* bih1 = (const float*)d_in[10];
    const float* bhh1 = (const float*)d_in[11];
    const float* Wg1  = (const float*)d_in[12];
    const float* bg1  = (const float*)d_in[13];
    const float* Wg2  = (const float*)d_in[14];
    const float* bg2  = (const float*)d_in[15];
    const float* Wg3  = (const float*)d_in[16];
    const float* bg3  = (const float*)d_in[17];
    const float* Wg4  = (const float*)d_in[18];
    const float* bg4  = (const float*)d_in[19];
    const float* bng  = (const float*)d_in[20];
    const float* bnb  = (const float*)d_in[21];
    const float* fc1W = (const float*)d_in[22];
    const float* fc1b = (const float*)d_in[23];
    const float* fc2W = (const float*)d_in[24];
    const float* fc2b = (const float*)d_in[25];
    const float* fc3W = (const float*)d_in[26];
    const float* fc3b = (const float*)d_in[27];
    float* out = (float*)d_out;

    float *z, *y;
    cudaGetSymbolAddress((void**)&z, g_z);
    cudaGetSymbolAddress((void**)&y, g_y);

    reset_kernel<<<4, 256>>>();

    // fused persistent kernel: 16-CTA clusters, grid 96
    // (scan0 = CTAs 0-15, scan1 = 16-31, 64 workers: gx0, gx1, GCN-L1 z)
    cudaFuncSetAttribute(fused_kernel,
                         cudaFuncAttributeNonPortableClusterSizeAllowed, 1);
    {
        cudaLaunchConfig_t cfg = {};
        cfg.gridDim = dim3(96, 1, 1);
        cfg.blockDim = dim3(512, 1, 1);
        cfg.dynamicSmemBytes = 0;
        cfg.stream = 0;
        cudaLaunchAttribute attrs[1];
        attrs[0].id = cudaLaunchAttributeClusterDimension;
        attrs[0].val.clusterDim = {16, 1, 1};
        cfg.attrs = attrs;
        cfg.numAttrs = 1;
        cudaError_t err = cudaLaunchKernelEx(&cfg, fused_kernel,
            x, Wih0, bih0, bhh0, Whh0, Wih1, bih1, bhh1, Whh1, Wg1, 16);
        if (err != cudaSuccess) {
            cudaGetLastError();
            cudaLaunchConfig_t cfg2 = {};
            cfg2.gridDim = dim3(96, 1, 1);
            cfg2.blockDim = dim3(512, 1, 1);
            cfg2.dynamicSmemBytes = 0;
            cfg2.stream = 0;
            cudaLaunchAttribute attrs2[1];
            attrs2[0].id = cudaLaunchAttributeClusterDimension;
            attrs2[0].val.clusterDim = {8, 1, 1};
            cfg2.attrs = attrs2;
            cfg2.numAttrs = 1;
            cudaLaunchKernelEx(&cfg2, fused_kernel,
                x, Wih0, bih0, bhh0, Whh0, Wih1, bih1, bhh1, Whh1, Wg1, 8);
        }
    }

    // ---- GCN layer 1: z computed inside fused kernel ----
    {
        init_bias_kernel<<<(NND * 320 + 255) / 256, 256>>>(y, bg1, 320);
        long long st4 = (long long)EE * (320 / 4);
        scatter_kernel<4><<<(unsigned)((st4 + 255) / 256), 256>>>(z, ei, ew, y, 320);
    }

    // ---- GCN layers 2-4 ----
    const int fdims[4] = {320, 180, 90, 50};
    const float* gw[3] = {Wg2, Wg3, Wg4};
    const float* gb[3] = {bg2, bg3, bg4};
    for (int L = 0; L < 3; L++) {
        int Kf = fdims[L], Nf = fdims[L + 1];
        dim3 grid((Nf + 63) / 64, NND / 128);
        sgemm_kernel<0, 1><<<grid, 256>>>(NND, Nf, Kf, y, gw[L], z, nullptr, nullptr);
        init_bias_kernel<<<(NND * Nf + 255) / 256, 256>>>(y, gb[L], Nf);
        if (Nf % 4 == 0) {
            long long st4 = (long long)EE * (Nf / 4);
            scatter_kernel<4><<<(unsigned)((st4 + 255) / 256), 256>>>(z, ei, ew, y, Nf);
        } else {
            long long st2 = (long long)EE * (Nf / 2);
            scatter_kernel<2><<<(unsigned)((st2 + 255) / 256), 256>>>(z, ei, ew, y, Nf);
        }
    }

    bn_stats_kernel<<<50, 256>>>(y);
    bn_pool_fc_kernel<<<(GGR + 127) / 128, 128>>>(
        y, bng, bnb, fc1W, fc1b, fc2W, fc2b, fc3W, fc3b, out);
}

// round 17
// speedup vs baseline: 1.7060x; 1.7060x over previous
#include <cuda_runtime.h>
#include <cooperative_groups.h>
#include <math.h>

namespace cg = cooperative_groups;

#define NND   8192
#define FIN   1280
#define HH    320
#define EE    131072
#define GGR   1024
#define CHUNK 128
#define NCH   (NND / CHUNK)        // 64 chunks
#define NTILE (FIN / 128)          // 10 n-tiles per chunk
#define TASKS_PER (NCH * NTILE)    // 640

// ---------------- scratch (device globals) ----------------
__device__ float g_gx0[NND * FIN];
__device__ float g_gx1[NND * FIN];
__device__ float g_h0[NND * HH];
__device__ float g_h1[NND * HH];
__device__ float g_z [NND * HH];
__device__ float g_y [NND * HH];
__device__ float g_mu[64];
__device__ float g_rstd[64];
__device__ int   g_cnt0[NCH];
__device__ int   g_cnt1[NCH];
__device__ int   g_hflag[NCH * 16];
__device__ int   g_q;

__device__ __forceinline__ float lrelu(float x) { return x > 0.f ? x : 0.01f * x; }

// HW tanh approx (MUFU.TANH): verified rel_err-neutral since R7
__device__ __forceinline__ float tanha(float x) {
    float r;
    asm("tanh.approx.f32 %0, %1;" : "=f"(r) : "f"(x));
    return r;
}
__device__ __forceinline__ float sigma(float x) {
    return fmaf(0.5f, tanha(0.5f * x), 0.5f);
}

__device__ __forceinline__ unsigned s2u(const void* p) {
    unsigned a;
    asm("{ .reg .u64 t; cvta.to.shared.u64 t, %1; cvt.u32.u64 %0, t; }" : "=r"(a) : "l"(p));
    return a;
}
__device__ __forceinline__ int ld_acq(const int* p) {
    int v;
    asm volatile("ld.global.acquire.gpu.s32 %0, [%1];" : "=r"(v) : "l"(p));
    return v;
}
__device__ __forceinline__ void st_rel(int* p, int v) {
    asm volatile("st.global.release.gpu.s32 [%0], %1;" :: "l"(p), "r"(v));
}

// packed fp32x2 fma helpers
__device__ __forceinline__ void fma2(unsigned long long& d,
                                     unsigned long long a, unsigned long long b) {
    asm("fma.rn.f32x2 %0, %1, %2, %0;" : "+l"(d) : "l"(a), "l"(b));
}
__device__ __forceinline__ unsigned long long pack2(float lo, float hi) {
    unsigned long long r;
    asm("mov.b64 %0, {%1, %2};" : "=l"(r) : "f"(lo), "f"(hi));
    return r;
}
__device__ __forceinline__ void unpack2(unsigned long long v, float& lo, float& hi) {
    asm("mov.b64 {%0, %1}, %2;" : "=f"(lo), "=f"(hi) : "l"(v));
}

__device__ __forceinline__ void mbar_init(unsigned addr, unsigned cnt) {
    asm volatile("mbarrier.init.shared.b64 [%0], %1;" :: "r"(addr), "r"(cnt) : "memory");
}
__device__ __forceinline__ void mbar_arrive_local(unsigned addr) {
    asm volatile("mbarrier.arrive.shared.b64 _, [%0];" :: "r"(addr) : "memory");
}
__device__ __forceinline__ void mbar_expect_tx(unsigned addr, unsigned bytes) {
    asm volatile("mbarrier.arrive.expect_tx.shared.b64 _, [%0], %1;"
                 :: "r"(addr), "r"(bytes) : "memory");
}
__device__ __forceinline__ void mbar_wait(unsigned addr, unsigned parity) {
    asm volatile(
        "{\n\t"
        ".reg .pred P;\n\t"
        "WLP_%=:\n\t"
        "mbarrier.try_wait.parity.acquire.cluster.shared::cta.b64 P, [%0], %1, 0x989680;\n\t"
        "@P bra WDN_%=;\n\t"
        "bra WLP_%=;\n\t"
        "WDN_%=:\n\t"
        "}"
        :: "r"(addr), "r"(parity) : "memory");
}
__device__ __forceinline__ unsigned mapa_rank(unsigned addr, unsigned rank) {
    unsigned r;
    asm("mapa.shared::cluster.u32 %0, %1, %2;" : "=r"(r) : "r"(addr), "r"(rank));
    return r;
}
__device__ __forceinline__ void st_async64(unsigned daddr, unsigned maddr,
                                           unsigned long long val) {
    asm volatile(
        "st.async.shared::cluster.mbarrier::complete_tx::bytes.b64 [%0], %1, [%2];"
        :: "r"(daddr), "l"(val), "r"(maddr) : "memory");
}

// ---------------- worker: 128x128 fp32 tile GEMM (512 threads) ----------------
__device__ void gemm_tile_128(const float* __restrict__ A, int lda,
                              const float* __restrict__ B, int ldb,
                              float* __restrict__ C, int ldc, int K,
                              const float* __restrict__ b0,
                              const float* __restrict__ b1)
{
    __shared__ __align__(16) float As[16][132];
    __shared__ __align__(16) float Bs[16][136];
    const int tid = threadIdx.x;
    const int tx = tid & 31;
    const int ty = tid >> 5;

    float acc[8][4];
#pragma unroll
    for (int i = 0; i < 8; i++)
#pragma unroll
        for (int j = 0; j < 4; j++) acc[i][j] = 0.f;

    for (int k0 = 0; k0 < K; k0 += 16) {
#pragma unroll
        for (int r = 0; r < 4; r++) {
            int idx = tid + r * 512;
            int m = idx >> 4, kk = idx & 15;
            As[kk][m] = A[(size_t)m * lda + k0 + kk];
        }
#pragma unroll
        for (int r = 0; r < 4; r++) {
            int idx = tid + r * 512;
            int n = idx >> 4, kk = idx & 15;
            Bs[kk][n] = B[(size_t)n * ldb + k0 + kk];
        }
        __syncthreads();
#pragma unroll
        for (int kk = 0; kk < 16; kk++) {
            float4 b = *(const float4*)&Bs[kk][tx * 4];
            float a[8];
#pragma unroll
            for (int i = 0; i < 8; i++) a[i] = As[kk][ty * 8 + i];
#pragma unroll
            for (int i = 0; i < 8; i++) {
                acc[i][0] = fmaf(a[i], b.x, acc[i][0]);
                acc[i][1] = fmaf(a[i], b.y, acc[i][1]);
                acc[i][2] = fmaf(a[i], b.z, acc[i][2]);
                acc[i][3] = fmaf(a[i], b.w, acc[i][3]);
            }
        }
        __syncthreads();
    }
#pragma unroll
    for (int i = 0; i < 8; i++) {
        int m = ty * 8 + i;
#pragma unroll
        for (int j = 0; j < 4; j++) {
            int n = tx * 4 + j;
            C[(size_t)m * ldc + n] = acc[i][j] + b0[n] + b1[n];
        }
    }
}

__device__ void worker_body(const float* __restrict__ x,
                            const float* __restrict__ Wih0,
                            const float* __restrict__ bih0,
                            const float* __restrict__ bhh0,
                            const float* __restrict__ Wih1,
                            const float* __restrict__ bih1,
                            const float* __restrict__ bhh1,
                            int ncta)
{
    __shared__ int task_s;
    const int tid = threadIdx.x;
    for (;;) {
        if (tid == 0) task_s = atomicAdd(&g_q, 1);
        __syncthreads();
        const int task = task_s;
        __syncthreads();
        if (task >= 2 * TASKS_PER) return;
        if (task < TASKS_PER) {
            int k = task / NTILE, nt = task % NTILE;
            gemm_tile_128(x + (size_t)k * CHUNK * FIN, FIN,
                          Wih0 + (size_t)nt * 128 * FIN, FIN,
                          g_gx0 + (size_t)k * CHUNK * FIN + nt * 128, FIN, FIN,
                          bih0 + nt * 128, bhh0 + nt * 128);
            __threadfence();
            __syncthreads();
            if (tid == 0) atomicAdd(&g_cnt0[k], 1);
        } else {
            int t2 = task - TASKS_PER;
            int k = t2 / NTILE, nt = t2 % NTILE;
            if (tid == 0) {
                for (int r = 0; r < ncta; r++)
                    while (ld_acq(&g_hflag[k * 16 + r]) == 0) __nanosleep(200);
            }
            __syncthreads();
            gemm_tile_128(g_h0 + (size_t)k * CHUNK * HH, HH,
                          Wih1 + (size_t)nt * 128 * HH, HH,
                          g_gx1 + (size_t)k * CHUNK * FIN + nt * 128, FIN, HH,
                          bih1 + nt * 128, bhh1 + nt * 128);
            __threadfence();
            __syncthreads();
            if (tid == 0) atomicAdd(&g_cnt1[k], 1);
        }
    }
}

// ---------------- LSTM scan: R8 body EXACT (proven 7.37ms) ----------------
template<int NCTA, int EMIT>
__device__ void scan_body(const float* __restrict__ gx,
                          const float* __restrict__ Whh,
                          float* __restrict__ hs,
                          int* __restrict__ cnt)
{
    constexpr int U  = HH / NCTA;
    constexpr int RW = (4 * U) / 16;

    cg::cluster_group cluster = cg::this_cluster();
    const unsigned rank = cluster.block_rank();
    const int tid = threadIdx.x;
    const int w = tid >> 5, lane = tid & 31;

    __shared__ alignas(8) float h_s[2][HH];
    __shared__ alignas(8) float gates_s[4 * U];
    __shared__ alignas(8) float c_s[U];
    __shared__ alignas(8) unsigned long long mbar[2];

    const unsigned mb0 = s2u(&mbar[0]);
    const unsigned mb1 = s2u(&mbar[1]);

    unsigned long long wr2[RW][5];
#pragma unroll
    for (int rr = 0; rr < RW; rr++) {
        int r = w * RW + rr;
        int gate = r / U;
        int jj = r - gate * U;
        int grow = gate * HH + (int)rank * U + jj;
        const float2* wp = (const float2*)(Whh + (size_t)grow * HH);
#pragma unroll
        for (int p = 0; p < 5; p++) {
            float2 v = wp[lane + 32 * p];
            wr2[rr][p] = pack2(v.x, v.y);
        }
    }

    if (tid < HH) h_s[0][tid] = 0.f;
    if (tid < U) c_s[tid] = 0.f;
    if (tid == 0) {
        mbar_init(mb0, 1);
        mbar_init(mb1, 1);
        mbar_arrive_local(mb0);        // buf0 phase 0: h=0 preloaded
        mbar_expect_tx(mb1, 1280);     // buf1 phase 0 = step-0 writes
    }
    cluster.sync();

    const int jg = (int)rank * U + 2 * tid;     // valid tid < U/2
    const float* gxp = gx + jg;

    unsigned dmap[NCTA], mmap[NCTA];
    if (tid < U / 2) {
        const unsigned ha0 = s2u(&h_s[0][jg]);
#pragma unroll
        for (unsigned r = 0; r < (unsigned)NCTA; r++) {
            dmap[r] = mapa_rank(ha0, r);
            mmap[r] = mapa_rank(mb0, r);
        }
    }

    for (int t = 0; t < NND; t++) {
        if ((t & (CHUNK - 1)) == 0) {
            if (tid == 0) {
                int k = t >> 7;
                while (ld_acq(&cnt[k]) < NTILE) __nanosleep(100);
            }
            __syncthreads();
        }

        const int cur = t & 1;
        const unsigned mcur = cur ? mb1 : mb0;

        float2 gxv[4];
        if (tid < U / 2) {
#pragma unroll
            for (int g = 0; g < 4; g++)
                gxv[g] = __ldg((const float2*)(gxp + (size_t)t * FIN + g * HH));
        }

        if (t > 0) mbar_wait(mcur, (t >> 1) & 1);
        if (tid == 32) mbar_expect_tx(mcur, 1280);

        const float2* hp = (const float2*)h_s[cur];
        unsigned long long acc2[RW];
#pragma unroll
        for (int rr = 0; rr < RW; rr++) acc2[rr] = 0ULL;
#pragma unroll
        for (int p = 0; p < 5; p++) {
            float2 hv = hp[lane + 32 * p];
            unsigned long long hv2 = pack2(hv.x, hv.y);
#pragma unroll
            for (int rr = 0; rr < RW; rr++) fma2(acc2[rr], wr2[rr][p], hv2);
        }
        float s[RW];
#pragma unroll
        for (int rr = 0; rr < RW; rr++) {
            float a0, a1;
            unpack2(acc2[rr], a0, a1);
            s[rr] = a0 + a1;
        }
#pragma unroll
        for (int off = 16; off > 0; off >>= 1)
#pragma unroll
            for (int rr = 0; rr < RW; rr++)
                s[rr] += __shfl_xor_sync(0xffffffffu, s[rr], off);
        if (lane == 0) {
#pragma unroll
            for (int rr = 0; rr < RW; rr++) gates_s[w * RW + rr] = s[rr];
        }
        __syncthreads();

        if (tid < U / 2) {
            const float2* gp = (const float2*)gates_s;
            float2 Gi = gp[tid];
            float2 Gf = gp[U / 2 + tid];
            float2 Gg = gp[U + tid];
            float2 Go = gp[3 * U / 2 + tid];
            float i0 = Gi.x + gxv[0].x, i1 = Gi.y + gxv[0].y;
            float f0 = Gf.x + gxv[1].x, f1 = Gf.y + gxv[1].y;
            float g0 = Gg.x + gxv[2].x, g1 = Gg.y + gxv[2].y;
            float o0 = Go.x + gxv[3].x, o1 = Go.y + gxv[3].y;
            float2 c = *(float2*)&c_s[2 * tid];
            c.x = sigma(f0) * c.x + sigma(i0) * tanha(g0);
            c.y = sigma(f1) * c.y + sigma(i1) * tanha(g1);
            float h0v = sigma(o0) * tanha(c.x);
            float h1v = sigma(o1) * tanha(c.y);
            *(float2*)&c_s[2 * tid] = c;
            unsigned long long hh = pack2(h0v, h1v);
            *(unsigned long long*)&hs[(size_t)t * HH + jg] = hh;
            const unsigned doff = (cur ^ 1) ? (unsigned)(HH * 4) : 0u;
            const unsigned moff = (cur ^ 1) ? 8u : 0u;
#pragma unroll
            for (unsigned r = 0; r < (unsigned)NCTA; r++)
                st_async64(dmap[r] + doff, mmap[r] + moff, hh);
        }

        if (EMIT && (t & (CHUNK - 1)) == (CHUNK - 1)) {
            __threadfence();
            __syncthreads();
            if (tid == 0) st_rel(&g_hflag[(t >> 7) * 16 + (int)rank], 1);
        }
    }

    // exit drain
    mbar_wait(mb0, (NND >> 1) & 1);
    cluster.sync();
}

// ---------------- fused persistent kernel ----------------
__global__ void __launch_bounds__(512, 1)
fused_kernel(const float* __restrict__ x,
             const float* __restrict__ Wih0, const float* __restrict__ bih0,
             const float* __restrict__ bhh0, const float* __restrict__ Whh0,
             const float* __restrict__ Wih1, const float* __restrict__ bih1,
             const float* __restrict__ bhh1, const float* __restrict__ Whh1,
             int ncta)
{
    const int bid = blockIdx.x;
    if (ncta == 16) {
        if (bid < 16)      scan_body<16, 1>(g_gx0, Whh0, g_h0, g_cnt0);
        else if (bid < 32) scan_body<16, 0>(g_gx1, Whh1, g_h1, g_cnt1);
        else               worker_body(x, Wih0, bih0, bhh0, Wih1, bih1, bhh1, 16);
    } else {
        if (bid < 8)       scan_body<8, 1>(g_gx0, Whh0, g_h0, g_cnt0);
        else if (bid < 16) scan_body<8, 0>(g_gx1, Whh1, g_h1, g_cnt1);
        else               worker_body(x, Wih0, bih0, bhh0, Wih1, bih1, bhh1, 8);
    }
}

__global__ void reset_kernel()
{
    int i = blockIdx.x * blockDim.x + threadIdx.x;
    if (i < NCH) { g_cnt0[i] = 0; g_cnt1[i] = 0; }
    if (i < NCH * 16) g_hflag[i] = 0;
    if (i == 0) g_q = 0;
}

// ---------------- GCN-path fp32 GEMM ----------------
template<int TRANSB, int LRA>
__global__ void __launch_bounds__(256) sgemm_kernel(
    int M, int N, int K,
    const float* __restrict__ A, const float* __restrict__ B,
    float* __restrict__ C,
    const float* __restrict__ bias0, const float* __restrict__ bias1)
{
    __shared__ float As[16][132];
    __shared__ float Bs[16][68];
    const int tid = threadIdx.x;
    const int tx = tid & 15;
    const int ty = tid >> 4;
    const int bm = blockIdx.y * 128;
    const int bn = blockIdx.x * 64;

    float acc[8][4];
#pragma unroll
    for (int i = 0; i < 8; i++)
#pragma unroll
        for (int j = 0; j < 4; j++) acc[i][j] = 0.f;

    for (int k0 = 0; k0 < K; k0 += 16) {
#pragma unroll
        for (int r = 0; r < 8; r++) {
            int idx = tid + r * 256;
            int m = idx >> 4, kk = idx & 15;
            int kg = k0 + kk;
            float v = 0.f;
            if (kg < K) {
                v = A[(size_t)(bm + m) * K + kg];
                if (LRA) v = lrelu(v);
            }
            As[kk][m] = v;
        }
#pragma unroll
        for (int r = 0; r < 4; r++) {
            int idx = tid + r * 256;
            float v = 0.f;
            if (TRANSB) {
                int nn = idx >> 4, kk = idx & 15;
                if (bn + nn < N && k0 + kk < K) v = B[(size_t)(bn + nn) * K + k0 + kk];
                Bs[kk][nn] = v;
            } else {
                int kk = idx >> 6, nn = idx & 63;
                if (k0 + kk < K && bn + nn < N) v = B[(size_t)(k0 + kk) * N + bn + nn];
                Bs[kk][nn] = v;
            }
        }
        __syncthreads();
#pragma unroll
        for (int kk = 0; kk < 16; kk++) {
            float a[8], b[4];
#pragma unroll
            for (int i = 0; i < 8; i++) a[i] = As[kk][ty * 8 + i];
#pragma unroll
            for (int j = 0; j < 4; j++) b[j] = Bs[kk][tx * 4 + j];
#pragma unroll
            for (int i = 0; i < 8; i++)
#pragma unroll
                for (int j = 0; j < 4; j++) acc[i][j] = fmaf(a[i], b[j], acc[i][j]);
        }
        __syncthreads();
    }
#pragma unroll
    for (int i = 0; i < 8; i++) {
        int m = bm + ty * 8 + i;
#pragma unroll
        for (int j = 0; j < 4; j++) {
            int n = bn + tx * 4 + j;
            if (n < N) {
                float v = acc[i][j];
                if (bias0) v += bias0[n];
                if (bias1) v += bias1[n];
                C[(size_t)m * N + n] = v;
            }
        }
    }
}

// ---------------- GCN scatter (vector atomics) ----------------
__global__ void init_bias_kernel(float* __restrict__ y, const float* __restrict__ b, int F)
{
    int idx = blockIdx.x * 256 + threadIdx.x;
    if (idx < NND * F) y[idx] = b[idx % F];
}

template<int VEC>
__global__ void scatter_kernel(const float* __restrict__ z, const int* __restrict__ ei,
                               const float* __restrict__ ew, float* __restrict__ y, int F)
{
    long long idx = (long long)blockIdx.x * blockDim.x + threadIdx.x;
    int nv = F / VEC;
    long long total = (long long)EE * nv;
    if (idx >= total) return;
    int e  = (int)(idx / nv);
    int fv = (int)(idx - (long long)e * nv);
    int s = ei[e];
    int d = ei[EE + e];
    float wv = ew[e];
    if (VEC == 4) {
        float4 v = *(const float4*)(z + (size_t)s * F + 4 * fv);
        float4 m = make_float4(v.x * wv, v.y * wv, v.z * wv, v.w * wv);
        atomicAdd((float4*)(y + (size_t)d * F + 4 * fv), m);
    } else {
        float2 v = *(const float2*)(z + (size_t)s * F + 2 * fv);
        float2 m = make_float2(v.x * wv, v.y * wv);
        atomicAdd((float2*)(y + (size_t)d * F + 2 * fv), m);
    }
}

// ---------------- BatchNorm stats ----------------
__global__ void bn_stats_kernel(const float* __restrict__ y)
{
    int f = blockIdx.x;
    int tid = threadIdx.x;
    __shared__ float red[256];
    __shared__ float mu_s;

    float s = 0.f;
    for (int i = tid; i < NND; i += 256) s += y[(size_t)i * 50 + f];
    red[tid] = s; __syncthreads();
    for (int st = 128; st > 0; st >>= 1) {
        if (tid < st) red[tid] += red[tid + st];
        __syncthreads();
    }
    if (tid == 0) mu_s = red[0] * (1.f / (float)NND);
    __syncthreads();
    float mu = mu_s;

    float s2 = 0.f;
    for (int i = tid; i < NND; i += 256) {
        float d = y[(size_t)i * 50 + f] - mu;
        s2 += d * d;
    }
    red[tid] = s2; __syncthreads();
    for (int st = 128; st > 0; st >>= 1) {
        if (tid < st) red[tid] += red[tid + st];
        __syncthreads();
    }
    if (tid == 0) {
        g_mu[f] = mu;
        g_rstd[f] = rsqrtf(red[0] * (1.f / (float)NND) + 1e-5f);
    }
}

// ---------------- BN apply + lrelu + pool + FC ----------------
__global__ void __launch_bounds__(128) bn_pool_fc_kernel(
    const float* __restrict__ y,
    const float* __restrict__ gamma, const float* __restrict__ beta,
    const float* __restrict__ fc1W, const float* __restrict__ fc1b,
    const float* __restrict__ fc2W, const float* __restrict__ fc2b,
    const float* __restrict__ fc3W, const float* __restrict__ fc3b,
    float* __restrict__ out)
{
    int g = blockIdx.x * blockDim.x + threadIdx.x;
    if (g >= GGR) return;

    float pooled[50];
#pragma unroll
    for (int f = 0; f < 50; f++) pooled[f] = 0.f;
    for (int k = 0; k < 8; k++) {
        const float* row = y + (size_t)(g * 8 + k) * 50;
#pragma unroll
        for (int f = 0; f < 50; f++) {
            float v = row[f];
            float bn = gamma[f] * (v - g_mu[f]) * g_rstd[f] + beta[f];
            pooled[f] += lrelu(bn);
        }
    }
    float h1[30];
    for (int n = 0; n < 30; n++) {
        float s = fc1b[n];
#pragma unroll
        for (int k = 0; k < 50; k++) s = fmaf(pooled[k], fc1W[k * 30 + n], s);
        h1[n] = lrelu(s);
    }
    float h2[20];
    for (int n = 0; n < 20; n++) {
        float s = fc2b[n];
#pragma unroll
        for (int k = 0; k < 30; k++) s = fmaf(h1[k], fc2W[k * 20 + n], s);
        h2[n] = lrelu(s);
    }
    for (int n = 0; n < 2; n++) {
        float s = fc3b[n];
#pragma unroll
        for (int k = 0; k < 20; k++) s = fmaf(h2[k], fc3W[k * 2 + n], s);
        out[g * 2 + n] = lrelu(s);
    }
}

// ---------------- launch ----------------
extern "C" void kernel_launch(void* const* d_in, const int* in_sizes, int n_in,
                              void* d_out, int out_size)
{
    const float* x    = (const float*)d_in[0];
    const int*   ei   = (const int*)  d_in[1];
    const float* ew   = (const float*)d_in[2];
    const float* Wih0 = (const float*)d_in[4];
    const float* Whh0 = (const float*)d_in[5];
    const float* bih0 = (const float*)d_in[6];
    const float* bhh0 = (const float*)d_in[7];
    const float* Wih1 = (const float*)d_in[8];
    const float* Whh1 = (const float*)d_in[9];
    const float* bih1 = (const float*)d_in[10];
    const float* bhh1 = (const float*)d_in[11];
    const float* Wg1  = (const float*)d_in[12];
    const float* bg1  = (const float*)d_in[13];
    const float* Wg2  = (const float*)d_in[14];
    const float* bg2  = (const float*)d_in[15];
    const float* Wg3  = (const float*)d_in[16];
    const float* bg3  = (const float*)d_in[17];
    const float* Wg4  = (const float*)d_in[18];
    const float* bg4  = (const float*)d_in[19];
    const float* bng  = (const float*)d_in[20];
    const float* bnb  = (const float*)d_in[21];
    const float* fc1W = (const float*)d_in[22];
    const float* fc1b = (const float*)d_in[23];
    const float* fc2W = (const float*)d_in[24];
    const float* fc2b = (const float*)d_in[25];
    const float* fc3W = (const float*)d_in[26];
    const float* fc3b = (const float*)d_in[27];
    float* out = (float*)d_out;

    float *h1, *z, *y;
    cudaGetSymbolAddress((void**)&h1, g_h1);
    cudaGetSymbolAddress((void**)&z,  g_z);
    cudaGetSymbolAddress((void**)&y,  g_y);

    reset_kernel<<<4, 256>>>();

    // fused persistent kernel: 16-CTA clusters, grid 128 (R8 config exact)
    cudaFuncSetAttribute(fused_kernel,
                         cudaFuncAttributeNonPortableClusterSizeAllowed, 1);
    {
        cudaLaunchConfig_t cfg = {};
        cfg.gridDim = dim3(128, 1, 1);
        cfg.blockDim = dim3(512, 1, 1);
        cfg.dynamicSmemBytes = 0;
        cfg.stream = 0;
        cudaLaunchAttribute attrs[1];
        attrs[0].id = cudaLaunchAttributeClusterDimension;
        attrs[0].val.clusterDim = {16, 1, 1};
        cfg.attrs = attrs;
        cfg.numAttrs = 1;
        cudaError_t err = cudaLaunchKernelEx(&cfg, fused_kernel,
            x, Wih0, bih0, bhh0, Whh0, Wih1, bih1, bhh1, Whh1, 16);
        if (err != cudaSuccess) {
            cudaGetLastError();
            cudaLaunchConfig_t cfg2 = {};
            cfg2.gridDim = dim3(144, 1, 1);
            cfg2.blockDim = dim3(512, 1, 1);
            cfg2.dynamicSmemBytes = 0;
            cfg2.stream = 0;
            cudaLaunchAttribute attrs2[1];
            attrs2[0].id = cudaLaunchAttributeClusterDimension;
            attrs2[0].val.clusterDim = {8, 1, 1};
            cfg2.attrs = attrs2;
            cfg2.numAttrs = 1;
            cudaLaunchKernelEx(&cfg2, fused_kernel,
                x, Wih0, bih0, bhh0, Whh0, Wih1, bih1, bhh1, Whh1, 8);
        }
    }

    // ---- GCN chain (vectorized scatter atomics) ----
    const int fdims[5] = {320, 320, 180, 90, 50};
    const float* gw[4] = {Wg1, Wg2, Wg3, Wg4};
    const float* gb[4] = {bg1, bg2, bg3, bg4};
    const float* curA = h1;
    for (int L = 0; L < 4; L++) {
        int Kf = fdims[L], Nf = fdims[L + 1];
        dim3 grid((Nf + 63) / 64, NND / 128);
        sgemm_kernel<0, 1><<<grid, 256>>>(NND, Nf, Kf, curA, gw[L], z, nullptr, nullptr);
        init_bias_kernel<<<(NND * Nf + 255) / 256, 256>>>(y, gb[L], Nf);
        if (Nf % 4 == 0) {
            long long st4 = (long long)EE * (Nf / 4);
            scatter_kernel<4><<<(unsigned)((st4 + 255) / 256), 256>>>(z, ei, ew, y, Nf);
        } else {
            long long st2 = (long long)EE * (Nf / 2);
            scatter_kernel<2><<<(unsigned)((st2 + 255) / 256), 256>>>(z, ei, ew, y, Nf);
        }
        curA = y;
    }

    bn_stats_kernel<<<50, 256>>>(y);
    bn_pool_fc_kernel<<<(GGR + 127) / 128, 128>>>(
        y, bng, bnb, fc1W, fc1b, fc2W, fc2b, fc3W, fc3b, out);
}